// round 1
// baseline (speedup 1.0000x reference)
#include <cuda_runtime.h>

// Problem constants (fixed by setup_inputs): B=512, Np=128, Ng=128, TIME=5
#define BATCH 512
#define NP 128
#define NG 128
#define TSTEPS 5
#define GI (NG * TSTEPS)   // 640 interpolated gt points per batch

// Per-batch partial sums (no cudaMalloc allowed; use __device__ global scratch)
__device__ float g_partial[BATCH];

__device__ __forceinline__ float smooth_l1_elem(float d) {
    d = fabsf(d);
    return (d < 1.0f) ? (0.5f * d * d) : (d - 0.5f);
}

// One CTA per batch element. 128 threads: thread p owns pred point p.
__global__ void __launch_bounds__(128) dm_main(const float2* __restrict__ pred,
                                               const float2* __restrict__ gt) {
    __shared__ float2 interp[GI];   // 640 * 8B = 5120 B
    __shared__ float  red[128];

    const int b = blockIdx.x;
    const float2* gtb = gt + b * NG;

    // Build interpolation table: interp[n*5 + t] = gt[n]*s + gt[n-1]*(1-s), s = t/5
    for (int i = threadIdx.x; i < GI; i += 128) {
        int n = i / TSTEPS;
        int t = i - n * TSTEPS;
        float s = (float)t / (float)TSTEPS;
        float2 c  = gtb[n];
        float2 pv = gtb[(n + NG - 1) & (NG - 1)];   // roll(shift=1): index n-1 mod NG
        float2 v;
        v.x = c.x * s + pv.x * (1.0f - s);
        v.y = c.y * s + pv.y * (1.0f - s);
        interp[i] = v;
    }
    __syncthreads();

    // Each thread: argmin over 640 interp points (first occurrence on ties -> strict <)
    float2 pp = pred[b * NP + threadIdx.x];
    float best = 3.402823466e38f;
    int   bi   = 0;
    #pragma unroll 4
    for (int g = 0; g < GI; ++g) {
        float2 q = interp[g];               // broadcast read, conflict-free
        float dx = pp.x - q.x;
        float dy = pp.y - q.y;
        float d  = fmaf(dy, dy, dx * dx);
        if (d < best) { best = d; bi = g; }
    }

    float2 m = interp[bi];
    float l = smooth_l1_elem(pp.x - m.x) + smooth_l1_elem(pp.y - m.y);

    // Deterministic fixed-order block reduction
    red[threadIdx.x] = l;
    __syncthreads();
    #pragma unroll
    for (int s = 64; s > 0; s >>= 1) {
        if (threadIdx.x < s) red[threadIdx.x] += red[threadIdx.x + s];
        __syncthreads();
    }
    if (threadIdx.x == 0) g_partial[b] = red[0];
}

// Final deterministic reduction over 512 partials -> mean over B*NP*2 elements
__global__ void __launch_bounds__(256) dm_final(float* __restrict__ out) {
    __shared__ float red[256];
    float s = 0.0f;
    for (int i = threadIdx.x; i < BATCH; i += 256) s += g_partial[i];
    red[threadIdx.x] = s;
    __syncthreads();
    #pragma unroll
    for (int k = 128; k > 0; k >>= 1) {
        if (threadIdx.x < k) red[threadIdx.x] += red[threadIdx.x + k];
        __syncthreads();
    }
    if (threadIdx.x == 0) out[0] = red[0] / (float)(BATCH * NP * 2);
}

extern "C" void kernel_launch(void* const* d_in, const int* in_sizes, int n_in,
                              void* d_out, int out_size) {
    // metadata order: init_polys (unused), pred_poly, gt_polys
    const float2* pred = (const float2*)d_in[1];
    const float2* gt   = (const float2*)d_in[2];
    dm_main<<<BATCH, 128>>>(pred, gt);
    dm_final<<<1, 256>>>((float*)d_out);
}

// round 2
// speedup vs baseline: 1.3384x; 1.3384x over previous
#include <cuda_runtime.h>

// Fixed problem shape: B=512, Np=128, Ng=128, TIME=5
#define BATCH 512
#define NP 128
#define NG 128
#define TSTEPS 5
#define GI (NG * TSTEPS)   // 640 interpolated gt points

__device__ float        g_partial[BATCH];
__device__ unsigned int g_count = 0;

// ---------- packed f32x2 helpers (sm_103a) ----------
__device__ __forceinline__ unsigned long long pk2(float lo, float hi) {
    unsigned long long r;
    asm("mov.b64 %0, {%1, %2};" : "=l"(r) : "f"(lo), "f"(hi));
    return r;
}
__device__ __forceinline__ void unpk2(unsigned long long v, float& lo, float& hi) {
    asm("mov.b64 {%0, %1}, %2;" : "=f"(lo), "=f"(hi) : "l"(v));
}
__device__ __forceinline__ unsigned long long add2(unsigned long long a, unsigned long long b) {
    unsigned long long r;
    asm("add.rn.f32x2 %0, %1, %2;" : "=l"(r) : "l"(a), "l"(b));
    return r;
}
__device__ __forceinline__ unsigned long long mul2(unsigned long long a, unsigned long long b) {
    unsigned long long r;
    asm("mul.rn.f32x2 %0, %1, %2;" : "=l"(r) : "l"(a), "l"(b));
    return r;
}
__device__ __forceinline__ unsigned long long fma2(unsigned long long a, unsigned long long b,
                                                   unsigned long long c) {
    unsigned long long r;
    asm("fma.rn.f32x2 %0, %1, %2, %3;" : "=l"(r) : "l"(a), "l"(b), "l"(c));
    return r;
}

__device__ __forceinline__ float smooth_l1_elem(float d) {
    d = fabsf(d);
    return (d < 1.0f) ? (0.5f * d * d) : (d - 0.5f);
}

// One CTA per batch. 128 threads, thread p owns pred point p.
__global__ void __launch_bounds__(128) dm_fused(const float2* __restrict__ pred,
                                                const float2* __restrict__ gt,
                                                float* __restrict__ out) {
    __shared__ __align__(16) float nxs[GI];   // negated interp x
    __shared__ __align__(16) float nys[GI];   // negated interp y
    __shared__ float red[128];
    __shared__ int   s_is_last;

    const int b   = blockIdx.x;
    const int tid = threadIdx.x;
    const float2* gtb = gt + b * NG;

    // Build negated interpolation table (SoA):
    // interp[n*5+t] = gt[n]*s + gt[n-1]*(1-s), s = t/5; store -interp.
    for (int i = tid; i < GI; i += 128) {
        int n = i / TSTEPS;
        int t = i - n * TSTEPS;
        float s = (float)t / (float)TSTEPS;
        float2 c  = gtb[n];
        float2 pv = gtb[(n + NG - 1) & (NG - 1)];
        nxs[i] = -(c.x * s + pv.x * (1.0f - s));
        nys[i] = -(c.y * s + pv.y * (1.0f - s));
    }
    __syncthreads();

    const float2 pp = pred[b * NP + tid];
    const unsigned long long px2 = pk2(pp.x, pp.x);
    const unsigned long long py2 = pk2(pp.y, pp.y);

    // Branchless argmin: u = (float_bits(d) & ~0x3FF) | g ; min over u gives
    // first-occurrence argmin (d >= 0 so bits are uint-monotonic).
    const unsigned int MASK = 0xFFFFFC00u;
    unsigned int a0 = 0xFFFFFFFFu, a1 = 0xFFFFFFFFu, a2 = 0xFFFFFFFFu, a3 = 0xFFFFFFFFu;

    const float4* xs4 = reinterpret_cast<const float4*>(nxs);
    const float4* ys4 = reinterpret_cast<const float4*>(nys);

    #pragma unroll 4
    for (int j = 0; j < GI / 4; ++j) {
        float4 xv = xs4[j];                 // broadcast LDS.128
        float4 yv = ys4[j];
        // points 4j..4j+3
        unsigned long long dxa = add2(px2, pk2(xv.x, xv.y));
        unsigned long long dxb = add2(px2, pk2(xv.z, xv.w));
        unsigned long long dya = add2(py2, pk2(yv.x, yv.y));
        unsigned long long dyb = add2(py2, pk2(yv.z, yv.w));
        unsigned long long da  = fma2(dya, dya, mul2(dxa, dxa));
        unsigned long long db  = fma2(dyb, dyb, mul2(dxb, dxb));
        float d0, d1, d2, d3;
        unpk2(da, d0, d1);
        unpk2(db, d2, d3);
        unsigned int base = 4u * (unsigned int)j;
        a0 = min(a0, (__float_as_uint(d0) & MASK) | (base + 0u));
        a1 = min(a1, (__float_as_uint(d1) & MASK) | (base + 1u));
        a2 = min(a2, (__float_as_uint(d2) & MASK) | (base + 2u));
        a3 = min(a3, (__float_as_uint(d3) & MASK) | (base + 3u));
    }
    unsigned int best = min(min(a0, a1), min(a2, a3));
    int bi = (int)(best & 0x3FFu);

    float mx = -nxs[bi];
    float my = -nys[bi];
    float l = smooth_l1_elem(pp.x - mx) + smooth_l1_elem(pp.y - my);

    // Deterministic fixed-order block reduction
    red[tid] = l;
    __syncthreads();
    #pragma unroll
    for (int s = 64; s > 0; s >>= 1) {
        if (tid < s) red[tid] += red[tid + s];
        __syncthreads();
    }

    if (tid == 0) {
        g_partial[b] = red[0];
        __threadfence();
        unsigned int old = atomicAdd(&g_count, 1u);
        s_is_last = (old == (unsigned int)(gridDim.x - 1));
    }
    __syncthreads();

    if (s_is_last) {
        __threadfence();
        // Deterministic final reduction: fixed per-thread order, fixed tree.
        float s = __ldcg(&g_partial[tid])
                + __ldcg(&g_partial[tid + 128])
                + __ldcg(&g_partial[tid + 256])
                + __ldcg(&g_partial[tid + 384]);
        red[tid] = s;
        __syncthreads();
        #pragma unroll
        for (int k = 64; k > 0; k >>= 1) {
            if (tid < k) red[tid] += red[tid + k];
            __syncthreads();
        }
        if (tid == 0) {
            out[0] = red[0] * (1.0f / (float)(BATCH * NP * 2));
            g_count = 0;   // reset for next graph replay
        }
    }
}

extern "C" void kernel_launch(void* const* d_in, const int* in_sizes, int n_in,
                              void* d_out, int out_size) {
    const float2* pred = (const float2*)d_in[1];
    const float2* gt   = (const float2*)d_in[2];
    dm_fused<<<BATCH, 128>>>(pred, gt, (float*)d_out);
}